// round 5
// baseline (speedup 1.0000x reference)
#include <cuda_runtime.h>
#include <cuda_bf16.h>
#include <cstdint>

// Problem constants
constexpr int B_ = 16, S_ = 512, C_ = 16, D_ = 512;

// Scratch (device globals: allocation-free per harness rules)
__device__ __nv_bfloat16 g_vn[B_ * S_ * D_];          // normalized vis, bf16 (8 MB)
__device__ __nv_bfloat16 g_tn[B_ * C_ * S_ * D_];     // normalized text, transposed to (B,C,S,D), bf16 (128 MB)
__device__ float g_clip[B_ * C_];                      // clip_loss per (b, prompt)

#define DEVFN __device__ __forceinline__

DEVFN float warp_reduce_sum(float v) {
#pragma unroll
    for (int o = 16; o; o >>= 1) v += __shfl_xor_sync(0xffffffffu, v, o);
    return v;
}

// ---------------------------------------------------------------------------
// Kernel 1: normalize vis_feats (B,S,D) -> g_vn bf16. One warp per row.
// ---------------------------------------------------------------------------
__global__ void norm_vis_kernel(const float* __restrict__ vis) {
    int row = blockIdx.x * 8 + (threadIdx.x >> 5);     // 0 .. B*S-1
    int lane = threadIdx.x & 31;
    const float4* src = reinterpret_cast<const float4*>(vis + (size_t)row * D_);
    float4 v[4];
    float ss = 0.f;
#pragma unroll
    for (int j = 0; j < 4; ++j) {
        v[j] = src[lane + 32 * j];
        ss += v[j].x * v[j].x + v[j].y * v[j].y + v[j].z * v[j].z + v[j].w * v[j].w;
    }
    ss = warp_reduce_sum(ss);
    float inv = 1.f / fmaxf(sqrtf(ss), 1e-8f);
    __nv_bfloat162* dst = reinterpret_cast<__nv_bfloat162*>(g_vn + (size_t)row * D_);
#pragma unroll
    for (int j = 0; j < 4; ++j) {
        int c = lane + 32 * j;
        dst[2 * c]     = __floats2bfloat162_rn(v[j].x * inv, v[j].y * inv);
        dst[2 * c + 1] = __floats2bfloat162_rn(v[j].z * inv, v[j].w * inv);
    }
}

// ---------------------------------------------------------------------------
// Kernel 2: normalize text (B,S,C,D) -> g_tn bf16 transposed to (B,C,S,D).
// One warp per (b,s,c) row.
// ---------------------------------------------------------------------------
__global__ void norm_text_kernel(const float* __restrict__ txt) {
    int row = blockIdx.x * 8 + (threadIdx.x >> 5);     // (b*S + s)*C + c
    int lane = threadIdx.x & 31;
    int c = row & 15;
    int bs = row >> 4;
    int s = bs & 511;
    int b = bs >> 9;
    int orow = ((b * 16 + c) << 9) + s;                // (b*C + c)*S + s
    const float4* src = reinterpret_cast<const float4*>(txt + (size_t)row * D_);
    float4 v[4];
    float ss = 0.f;
#pragma unroll
    for (int j = 0; j < 4; ++j) {
        v[j] = src[lane + 32 * j];
        ss += v[j].x * v[j].x + v[j].y * v[j].y + v[j].z * v[j].z + v[j].w * v[j].w;
    }
    ss = warp_reduce_sum(ss);
    float inv = 1.f / fmaxf(sqrtf(ss), 1e-8f);
    __nv_bfloat162* dst = reinterpret_cast<__nv_bfloat162*>(g_tn + (size_t)orow * D_);
#pragma unroll
    for (int j = 0; j < 4; ++j) {
        int cc = lane + 32 * j;
        dst[2 * cc]     = __floats2bfloat162_rn(v[j].x * inv, v[j].y * inv);
        dst[2 * cc + 1] = __floats2bfloat162_rn(v[j].z * inv, v[j].w * inv);
    }
}

// ---------------------------------------------------------------------------
// Kernel 3: per (b,p) GEMM sim = Vn (512xD) @ Tn^T (512xD), fused exp/row/col
// sums + trace -> clip_loss. Grid = 256 blocks, 256 threads (8 warps).
// Block tile: strips of 256 rows x tiles of 64 cols, BK=32, double buffered.
// Warp layout: 4 (m) x 2 (n): each warp 64 rows x 32 cols.
// ---------------------------------------------------------------------------
DEVFN uint32_t smem_u32(const void* p) { return (uint32_t)__cvta_generic_to_shared(p); }

DEVFN void ldsm_x4(uint32_t& r0, uint32_t& r1, uint32_t& r2, uint32_t& r3, uint32_t addr) {
    asm volatile("ldmatrix.sync.aligned.m8n8.x4.shared.b16 {%0,%1,%2,%3}, [%4];"
                 : "=r"(r0), "=r"(r1), "=r"(r2), "=r"(r3) : "r"(addr));
}

DEVFN void mma16816(float* c, const uint32_t* a, const uint32_t* b) {
    asm volatile("mma.sync.aligned.m16n8k16.row.col.f32.bf16.bf16.f32 "
                 "{%0,%1,%2,%3}, {%4,%5,%6,%7}, {%8,%9}, {%0,%1,%2,%3};"
                 : "+f"(c[0]), "+f"(c[1]), "+f"(c[2]), "+f"(c[3])
                 : "r"(a[0]), "r"(a[1]), "r"(a[2]), "r"(a[3]), "r"(b[0]), "r"(b[1]));
}

// swizzle: 64B rows, 4x16B chunks; phys_chunk = kb ^ ((row>>1)&3)
DEVFN int swz(int row, int kb) { return kb ^ ((row >> 1) & 3); }

__global__ __launch_bounds__(256) void clip_gemm_kernel() {
    const int bid = blockIdx.x;                                     // b*16 + p
    const __nv_bfloat16* __restrict__ Ag = g_vn + (size_t)(bid >> 4) * (S_ * D_);
    const __nv_bfloat16* __restrict__ Bg = g_tn + (size_t)bid * (S_ * D_);

    __shared__ alignas(16) __nv_bfloat16 sA[2][256 * 32];           // 32 KB
    __shared__ alignas(16) __nv_bfloat16 sB[2][64 * 32];            // 8 KB
    __shared__ float s_rowsum[512];
    __shared__ float s_colsum[512];
    __shared__ float s_trace;
    __shared__ float s_red[8];

    const int tid = threadIdx.x;
    const int lane = tid & 31;
    const int warp = tid >> 5;
    const int wm = warp & 3;        // m-block: rows wm*64
    const int wn = warp >> 2;       // n-block: cols wn*32

    s_rowsum[tid] = 0.f; s_rowsum[tid + 256] = 0.f;
    s_colsum[tid] = 0.f; s_colsum[tid + 256] = 0.f;
    if (tid == 0) s_trace = 0.f;
    __syncthreads();

    // Global->shared assignments (per thread, per K-stage of BK=32)
    int goffA[4], soffA[4];
#pragma unroll
    for (int j = 0; j < 4; ++j) {
        int row = (tid >> 2) + 64 * j;
        int kb = tid & 3;
        goffA[j] = row * 512 + kb * 8;                  // elements
        soffA[j] = row * 32 + swz(row, kb) * 8;         // elements
    }
    const int rowb = tid >> 2, kbb = tid & 3;
    const int goffB = rowb * 512 + kbb * 8;
    const int soffB = rowb * 32 + swz(rowb, kbb) * 8;

    // ldmatrix byte offsets
    uint32_t aoff[4][2], boff[2][2];
    {
        int r16 = lane & 15;
        int koff = lane >> 4;
#pragma unroll
        for (int mi = 0; mi < 4; ++mi) {
            int r = wm * 64 + mi * 16 + r16;
#pragma unroll
            for (int ks = 0; ks < 2; ++ks) {
                int ch = ks * 2 + koff;
                aoff[mi][ks] = (uint32_t)((r * 32 + swz(r, ch) * 8) * 2);
            }
        }
        int rb8 = (lane & 7) + ((lane >> 4) << 3);
        int kob = (lane >> 3) & 1;
#pragma unroll
        for (int nj = 0; nj < 2; ++nj) {
            int r = wn * 32 + nj * 16 + rb8;
#pragma unroll
            for (int ks = 0; ks < 2; ++ks) {
                int ch = ks * 2 + kob;
                boff[nj][ks] = (uint32_t)((r * 32 + swz(r, ch) * 8) * 2);
            }
        }
    }
    const uint32_t baseA[2] = { smem_u32(&sA[0][0]), smem_u32(&sA[1][0]) };
    const uint32_t baseB[2] = { smem_u32(&sB[0][0]), smem_u32(&sB[1][0]) };

    const int r0 = lane >> 2;
    const int c0 = (lane & 3) * 2;
    float tr = 0.f;

#pragma unroll 1
    for (int strip = 0; strip < 2; ++strip) {
        float rowpart[8];
#pragma unroll
        for (int i = 0; i < 8; ++i) rowpart[i] = 0.f;

#pragma unroll 1
        for (int tt = 0; tt < 8; ++tt) {
            float acc[4][4][4];
#pragma unroll
            for (int mi = 0; mi < 4; ++mi)
#pragma unroll
                for (int nj = 0; nj < 4; ++nj)
#pragma unroll
                    for (int e = 0; e < 4; ++e) acc[mi][nj][e] = 0.f;

            const __nv_bfloat16* Ap = Ag + strip * 256 * 512;
            const __nv_bfloat16* Bp = Bg + tt * 64 * 512;

            uint4 ra[4], rb;
#pragma unroll
            for (int j = 0; j < 4; ++j) ra[j] = *reinterpret_cast<const uint4*>(Ap + goffA[j]);
            rb = *reinterpret_cast<const uint4*>(Bp + goffB);
#pragma unroll
            for (int j = 0; j < 4; ++j) *reinterpret_cast<uint4*>(&sA[0][soffA[j]]) = ra[j];
            *reinterpret_cast<uint4*>(&sB[0][soffB]) = rb;
            __syncthreads();

            int cur = 0;
#pragma unroll 1
            for (int kk = 0; kk < 16; ++kk) {
                if (kk < 15) {
                    const int k0 = (kk + 1) * 32;
#pragma unroll
                    for (int j = 0; j < 4; ++j)
                        ra[j] = *reinterpret_cast<const uint4*>(Ap + goffA[j] + k0);
                    rb = *reinterpret_cast<const uint4*>(Bp + goffB + k0);
                }
                const uint32_t bA = baseA[cur], bB = baseB[cur];
#pragma unroll
                for (int ks = 0; ks < 2; ++ks) {
                    uint32_t af[4][4], bf[2][4];
#pragma unroll
                    for (int mi = 0; mi < 4; ++mi)
                        ldsm_x4(af[mi][0], af[mi][1], af[mi][2], af[mi][3], bA + aoff[mi][ks]);
#pragma unroll
                    for (int nj = 0; nj < 2; ++nj)
                        ldsm_x4(bf[nj][0], bf[nj][1], bf[nj][2], bf[nj][3], bB + boff[nj][ks]);
#pragma unroll
                    for (int mi = 0; mi < 4; ++mi)
#pragma unroll
                        for (int n8 = 0; n8 < 4; ++n8)
                            mma16816(acc[mi][n8], af[mi], &bf[n8 >> 1][(n8 & 1) * 2]);
                }
                if (kk < 15) {
#pragma unroll
                    for (int j = 0; j < 4; ++j)
                        *reinterpret_cast<uint4*>(&sA[cur ^ 1][soffA[j]]) = ra[j];
                    *reinterpret_cast<uint4*>(&sB[cur ^ 1][soffB]) = rb;
                    __syncthreads();
                    cur ^= 1;
                }
            }
            __syncthreads();   // last reads of smem done before next tile's prologue stores

            // Epilogue: exp, row/col partial sums, trace
            float colpart[8];
#pragma unroll
            for (int i = 0; i < 8; ++i) colpart[i] = 0.f;
            const int vbase = strip * 256 + wm * 64;
            const int tb = tt * 64 + wn * 32;
#pragma unroll
            for (int mi = 0; mi < 4; ++mi)
#pragma unroll
                for (int n8 = 0; n8 < 4; ++n8)
#pragma unroll
                    for (int e = 0; e < 4; ++e) {
                        float val = acc[mi][n8][e];
                        float ex = __expf(val);
                        rowpart[mi * 2 + (e >> 1)] += ex;
                        colpart[n8 * 2 + (e & 1)] += ex;
                        int v = vbase + mi * 16 + (e >> 1) * 8 + r0;
                        int t = tb + n8 * 8 + (e & 1) + c0;
                        if (v == t) tr += val;
                    }
            // reduce colpart across lanes with same (lane&3)
#pragma unroll
            for (int off = 4; off < 32; off <<= 1)
#pragma unroll
                for (int i = 0; i < 8; ++i)
                    colpart[i] += __shfl_xor_sync(0xffffffffu, colpart[i], off);
            if (lane < 4) {
#pragma unroll
                for (int i = 0; i < 8; ++i) {
                    int t = tb + (i >> 1) * 8 + (i & 1) + lane * 2;
                    atomicAdd(&s_colsum[t], colpart[i]);
                }
            }
        } // tt

        // flush rowpart (reduce across lanes with same lane>>2)
#pragma unroll
        for (int off = 1; off < 4; off <<= 1)
#pragma unroll
            for (int i = 0; i < 8; ++i)
                rowpart[i] += __shfl_xor_sync(0xffffffffu, rowpart[i], off);
        if ((lane & 3) == 0) {
#pragma unroll
            for (int i = 0; i < 8; ++i) {
                int v = strip * 256 + wm * 64 + (i >> 1) * 16 + (i & 1) * 8 + (lane >> 2);
                atomicAdd(&s_rowsum[v], rowpart[i]);
            }
        }
    } // strip

    tr = warp_reduce_sum(tr);
    if (lane == 0) atomicAdd(&s_trace, tr);
    __syncthreads();

    float lsum = logf(s_rowsum[tid]) + logf(s_rowsum[tid + 256])
               + logf(s_colsum[tid]) + logf(s_colsum[tid + 256]);
    lsum = warp_reduce_sum(lsum);
    if (lane == 0) s_red[warp] = lsum;
    __syncthreads();
    if (tid == 0) {
        float tot = 0.f;
#pragma unroll
        for (int w = 0; w < 8; ++w) tot += s_red[w];
        g_clip[bid] = (0.5f * tot - s_trace) * (1.0f / 512.0f);
    }
}

// ---------------------------------------------------------------------------
// Kernel 4: finalize. loss = mean((output-clip)^2); acc; preds broadcast.
// out layout: [loss, acc, preds(B,S,1) as float]  (out_size expected 8194)
// ---------------------------------------------------------------------------
__global__ void finalize_kernel(const float* __restrict__ output,
                                float* __restrict__ out, int out_size) {
    __shared__ float s_sq[8];
    __shared__ int s_pred[16];
    __shared__ int s_match;
    const int tid = threadIdx.x;
    const int lane = tid & 31, warp = tid >> 5;
    if (tid == 0) s_match = 0;
    __syncthreads();

    float d = output[tid] - g_clip[tid];
    float sq = warp_reduce_sum(d * d);
    if (lane == 0) s_sq[warp] = sq;

    if (tid < 16) {
        int b = tid;
        float bo = output[b * 16], bc = g_clip[b * 16];
        int po = 0, pc = 0;
#pragma unroll
        for (int c = 1; c < 16; ++c) {
            float o = output[b * 16 + c];
            if (o < bo) { bo = o; po = c; }
            float cl = g_clip[b * 16 + c];
            if (cl < bc) { bc = cl; pc = c; }
        }
        s_pred[b] = po;
        if (po == pc) atomicAdd(&s_match, 1);
    }
    __syncthreads();

    if (tid == 0) {
        float tot = 0.f;
#pragma unroll
        for (int w = 0; w < 8; ++w) tot += s_sq[w];
        if (out_size > 0) out[0] = tot * (1.0f / 256.0f);
        if (out_size > 1) out[1] = (float)s_match * (100.0f / 16.0f);
    }
    for (int idx = tid; idx < 8192; idx += 256) {
        int b = idx >> 9;
        if (idx + 2 < out_size) out[idx + 2] = (float)s_pred[b];
    }
}

// ---------------------------------------------------------------------------
extern "C" void kernel_launch(void* const* d_in, const int* in_sizes, int n_in,
                              void* d_out, int out_size) {
    const float* output = (const float*)d_in[0];        // (B, C)
    const float* text   = (const float*)d_in[1];        // (B, S, C, D)
    const float* vis    = (const float*)d_in[2];        // (B, S, D)
    float* out = (float*)d_out;

    norm_vis_kernel<<<(B_ * S_) / 8, 256>>>(vis);
    norm_text_kernel<<<(B_ * S_ * C_) / 8, 256>>>(text);
    clip_gemm_kernel<<<B_ * C_, 256>>>();
    finalize_kernel<<<1, 256>>>(output, out, out_size);
}

// round 7
// speedup vs baseline: 1.0728x; 1.0728x over previous
#include <cuda_runtime.h>
#include <cuda_bf16.h>
#include <cstdint>

// Problem constants
constexpr int B_ = 16, S_ = 512, C_ = 16, D_ = 512;
constexpr float LOG2E = 1.4426950408889634f;
constexpr float LN2   = 0.6931471805599453f;

// Scratch (device globals: allocation-free per harness rules)
__device__ __nv_bfloat16 g_vn[B_ * S_ * D_];          // normalized vis * log2e, bf16 (8 MB)
__device__ __nv_bfloat16 g_tn[B_ * C_ * S_ * D_];     // normalized text, (B,C,S,D), bf16 (128 MB)
__device__ float g_rowsum[B_ * C_ * S_];               // per-(b,p) rowsum over v (512 KB)
__device__ float g_acc[B_ * C_];                       // 0.5 * sum log colsum (partial)
__device__ float g_diag[B_ * C_];                      // sum of diagonal cosines
__device__ float g_clip[B_ * C_];                      // clip_loss per (b, prompt)

#define DEVFN __device__ __forceinline__

DEVFN float warp_reduce_sum(float v) {
#pragma unroll
    for (int o = 16; o; o >>= 1) v += __shfl_xor_sync(0xffffffffu, v, o);
    return v;
}

DEVFN uint32_t smem_u32(const void* p) { return (uint32_t)__cvta_generic_to_shared(p); }
DEVFN float fast_exp2(float x) { float y; asm("ex2.approx.f32 %0, %1;" : "=f"(y) : "f"(x)); return y; }

DEVFN void cp_async16(uint32_t saddr, const void* gptr) {
    asm volatile("cp.async.cg.shared.global [%0], [%1], 16;" :: "r"(saddr), "l"(gptr));
}
#define CP_COMMIT() asm volatile("cp.async.commit_group;" ::: "memory")
#define CP_WAIT1()  asm volatile("cp.async.wait_group 1;" ::: "memory")
#define CP_WAIT0()  asm volatile("cp.async.wait_group 0;" ::: "memory")

DEVFN void ldsm_x4(uint32_t& r0, uint32_t& r1, uint32_t& r2, uint32_t& r3, uint32_t addr) {
    asm volatile("ldmatrix.sync.aligned.m8n8.x4.shared.b16 {%0,%1,%2,%3}, [%4];"
                 : "=r"(r0), "=r"(r1), "=r"(r2), "=r"(r3) : "r"(addr));
}

DEVFN void mma16816(float* c, const uint32_t* a, const uint32_t* b) {
    asm volatile("mma.sync.aligned.m16n8k16.row.col.f32.bf16.bf16.f32 "
                 "{%0,%1,%2,%3}, {%4,%5,%6,%7}, {%8,%9}, {%0,%1,%2,%3};"
                 : "+f"(c[0]), "+f"(c[1]), "+f"(c[2]), "+f"(c[3])
                 : "r"(a[0]), "r"(a[1]), "r"(a[2]), "r"(a[3]), "r"(b[0]), "r"(b[1]));
}

// swizzle: 64B rows, 4x16B chunks; phys_chunk = kb ^ ((row>>1)&3)
DEVFN int swz(int row, int kb) { return kb ^ ((row >> 1) & 3); }

// ---------------------------------------------------------------------------
// Kernel 1: normalize vis (B,S,D) -> g_vn bf16 scaled by log2e; also zero scratch.
// ---------------------------------------------------------------------------
__global__ void norm_vis_kernel(const float* __restrict__ vis) {
    const int tid = threadIdx.x;
    const int gtid = blockIdx.x * 256 + tid;
    if (gtid < B_ * C_ * S_) g_rowsum[gtid] = 0.f;
    if (gtid < B_ * C_) { g_acc[gtid] = 0.f; g_diag[gtid] = 0.f; }

    int row = blockIdx.x * 8 + (tid >> 5);
    int lane = tid & 31;
    const float4* src = reinterpret_cast<const float4*>(vis + (size_t)row * D_);
    float4 v[4];
    float ss = 0.f;
#pragma unroll
    for (int j = 0; j < 4; ++j) {
        v[j] = src[lane + 32 * j];
        ss += v[j].x * v[j].x + v[j].y * v[j].y + v[j].z * v[j].z + v[j].w * v[j].w;
    }
    ss = warp_reduce_sum(ss);
    float inv = LOG2E / fmaxf(sqrtf(ss), 1e-8f);
    __nv_bfloat162* dst = reinterpret_cast<__nv_bfloat162*>(g_vn + (size_t)row * D_);
#pragma unroll
    for (int j = 0; j < 4; ++j) {
        int c = lane + 32 * j;
        dst[2 * c]     = __floats2bfloat162_rn(v[j].x * inv, v[j].y * inv);
        dst[2 * c + 1] = __floats2bfloat162_rn(v[j].z * inv, v[j].w * inv);
    }
}

// ---------------------------------------------------------------------------
// Kernel 2: normalize text (B,S,C,D) -> g_tn bf16 transposed to (B,C,S,D);
// also accumulate diagonal dot(vn[b,s], tn[b,s,c]) into g_diag[b*16+c].
// ---------------------------------------------------------------------------
__global__ void norm_text_kernel(const float* __restrict__ txt) {
    int row = blockIdx.x * 8 + (threadIdx.x >> 5);     // (b*S + s)*C + c
    int lane = threadIdx.x & 31;
    int pc = row & 15;
    int bs = row >> 4;
    int s = bs & 511;
    int b = bs >> 9;
    int orow = ((b * 16 + pc) << 9) + s;
    const float4* src = reinterpret_cast<const float4*>(txt + (size_t)row * D_);
    float4 v[4];
    float ss = 0.f;
#pragma unroll
    for (int j = 0; j < 4; ++j) {
        v[j] = src[lane + 32 * j];
        ss += v[j].x * v[j].x + v[j].y * v[j].y + v[j].z * v[j].z + v[j].w * v[j].w;
    }
    ss = warp_reduce_sum(ss);
    float inv = 1.f / fmaxf(sqrtf(ss), 1e-8f);

    const __nv_bfloat162* vrow =
        reinterpret_cast<const __nv_bfloat162*>(g_vn + (size_t)(b * S_ + s) * D_);
    float dot = 0.f;
    __nv_bfloat162* dst = reinterpret_cast<__nv_bfloat162*>(g_tn + (size_t)orow * D_);
#pragma unroll
    for (int j = 0; j < 4; ++j) {
        int cc = lane + 32 * j;
        float2 a0 = __bfloat1622float2(vrow[2 * cc]);
        float2 a1 = __bfloat1622float2(vrow[2 * cc + 1]);
        dot += a0.x * (v[j].x * inv) + a0.y * (v[j].y * inv)
             + a1.x * (v[j].z * inv) + a1.y * (v[j].w * inv);
        dst[2 * cc]     = __floats2bfloat162_rn(v[j].x * inv, v[j].y * inv);
        dst[2 * cc + 1] = __floats2bfloat162_rn(v[j].z * inv, v[j].w * inv);
    }
    dot = warp_reduce_sum(dot);
    if (lane == 0) atomicAdd(&g_diag[(b << 4) + pc], dot * LN2);  // vn carries log2e
}

// ---------------------------------------------------------------------------
// Kernel 3: GEMM + fused exp/row/col sums. Grid 512: (b,p) x column half.
// Block: 512 vis rows (2 strips of 256) x 256 text cols (4 tiles of 64).
// 3-stage cp.async pipeline over 128 continuous K32 stages.
// Warp layout: 4(m) x 2(n); warp tile 64 x 32. 2 CTAs/SM.
// ---------------------------------------------------------------------------
constexpr uint32_t SA_BYTES = 16384;   // 256 rows x 64B (K32, SW)
constexpr uint32_t SB_BYTES = 4096;    // 64 rows x 64B
constexpr uint32_t OFF_A   = 0;        // 3 stages
constexpr uint32_t OFF_B   = 49152;    // 3 stages
constexpr uint32_t OFF_ROW = 61440;    // 512 f32
constexpr uint32_t OFF_COL = 63488;    // 256 f32
constexpr uint32_t OFF_RED = 64512;    // 8 f32
constexpr uint32_t DYN_BYTES = 64544 + 1024;

extern __shared__ char dynsmem[];

__global__ __launch_bounds__(256, 2) void clip_gemm_kernel() {
    const int tid = threadIdx.x, lane = tid & 31, warp = tid >> 5;
    const int wm = warp & 3;        // rows wm*64
    const int wn = warp >> 2;       // cols wn*32
    const int bid = blockIdx.x;
    const int bp = bid >> 1;        // b*16 + p
    const int ch = bid & 1;         // column half

    const char* Agc = reinterpret_cast<const char*>(g_vn + (size_t)(bp >> 4) * (S_ * D_));
    const char* Bgc = reinterpret_cast<const char*>(g_tn + (size_t)bp * (S_ * D_)
                                                    + (size_t)ch * 256 * D_);

    const uint32_t raw = smem_u32(dynsmem);
    const uint32_t sbase = (raw + 1023u) & ~1023u;
    char* gb = dynsmem + (sbase - raw);
    float* s_rowsum = (float*)(gb + OFF_ROW);
    float* s_colsum = (float*)(gb + OFF_COL);
    float* s_red    = (float*)(gb + OFF_RED);

    s_rowsum[tid] = 0.f; s_rowsum[tid + 256] = 0.f;
    s_colsum[tid & 255] = 0.f;

    // Per-thread cp.async offsets. A: 4 chunks of 16B; B: 1 chunk.
    uint32_t aG[4], aD[4];
#pragma unroll
    for (int j = 0; j < 4; ++j) {
        int row = (tid >> 2) + 64 * j;
        int kb = tid & 3;
        aG[j] = (uint32_t)(row * 1024 + kb * 16);                 // bytes in global row-major (512e rows)
        aD[j] = (uint32_t)((row * 32 + swz(row, kb) * 8) * 2);    // bytes in stage
    }
    const int rowb = tid >> 2, kbb = tid & 3;
    const uint32_t bG = (uint32_t)(rowb * 1024 + kbb * 16);
    const uint32_t bD = (uint32_t)((rowb * 32 + swz(rowb, kbb) * 8) * 2);

    // ldmatrix byte offsets within a stage
    uint32_t aoff[4][2], boff[2][2];
    {
        int r16 = lane & 15;
        int koff = lane >> 4;
#pragma unroll
        for (int mi = 0; mi < 4; ++mi) {
            int r = wm * 64 + mi * 16 + r16;
#pragma unroll
            for (int ks = 0; ks < 2; ++ks) {
                int chk = ks * 2 + koff;
                aoff[mi][ks] = (uint32_t)((r * 32 + swz(r, chk) * 8) * 2);
            }
        }
        int rb8 = (lane & 7) + ((lane >> 4) << 3);
        int kob = (lane >> 3) & 1;
#pragma unroll
        for (int nj = 0; nj < 2; ++nj) {
            int r = wn * 32 + nj * 16 + rb8;
#pragma unroll
            for (int ks = 0; ks < 2; ++ks) {
                int chk = ks * 2 + kob;
                boff[nj][ks] = (uint32_t)((r * 32 + swz(r, chk) * 8) * 2);
            }
        }
    }

    uint32_t A0 = sbase + OFF_A,              A1 = A0 + SA_BYTES, A2 = A1 + SA_BYTES;
    uint32_t Bb0 = sbase + OFF_B,             Bb1 = Bb0 + SB_BYTES, Bb2 = Bb1 + SB_BYTES;

    // stage st -> strip = st>>6, tt = (st>>4)&3, kk = st&15
    auto load_stage = [&](int st, uint32_t sA, uint32_t sB) {
        const char* Ap = Agc + (st >> 6) * 262144 + (st & 15) * 64;
        const char* Bp = Bgc + ((st >> 4) & 3) * 65536 + (st & 15) * 64;
#pragma unroll
        for (int j = 0; j < 4; ++j) cp_async16(sA + aD[j], Ap + aG[j]);
        cp_async16(sB + bD, Bp + bG);
    };

    float acc[4][4][4];
#pragma unroll
    for (int mi = 0; mi < 4; ++mi)
#pragma unroll
        for (int nj = 0; nj < 4; ++nj)
#pragma unroll
            for (int e = 0; e < 4; ++e) acc[mi][nj][e] = 0.f;
    float rowpart[8];
#pragma unroll
    for (int i = 0; i < 8; ++i) rowpart[i] = 0.f;

    // prologue
    load_stage(0, A0, Bb0); CP_COMMIT();
    load_stage(1, A1, Bb1); CP_COMMIT();

#pragma unroll 1
    for (int st = 0; st < 128; ++st) {
        if (st < 127) { CP_WAIT1(); } else { CP_WAIT0(); }
        __syncthreads();
        if (st + 2 < 128) { load_stage(st + 2, A2, Bb2); CP_COMMIT(); }

        // compute stage st (buffers A0/Bb0)
#pragma unroll
        for (int ks = 0; ks < 2; ++ks) {
            uint32_t af[4][4], bf[2][4];
#pragma unroll
            for (int mi = 0; mi < 4; ++mi)
                ldsm_x4(af[mi][0], af[mi][1], af[mi][2], af[mi][3], A0 + aoff[mi][ks]);
#pragma unroll
            for (int nj = 0; nj < 2; ++nj)
                ldsm_x4(bf[nj][0], bf[nj][1], bf[nj][2], bf[nj][3], Bb0 + boff[nj][ks]);
#pragma unroll
            for (int mi = 0; mi < 4; ++mi)
#pragma unroll
                for (int n8 = 0; n8 < 4; ++n8)
                    mma16816(acc[mi][n8], af[mi], &bf[n8 >> 1][(n8 & 1) * 2]);
        }

        if ((st & 15) == 15) {
            // tile epilogue: exp, row/col partial sums
            const int tt = (st >> 4) & 3;
            float colpart[8];
#pragma unroll
            for (int i = 0; i < 8; ++i) colpart[i] = 0.f;
#pragma unroll
            for (int mi = 0; mi < 4; ++mi)
#pragma unroll
                for (int n8 = 0; n8 < 4; ++n8)
#pragma unroll
                    for (int e = 0; e < 4; ++e) {
                        float ex = fast_exp2(acc[mi][n8][e]);   // A scaled by log2e
                        rowpart[mi * 2 + (e >> 1)] += ex;
                        colpart[n8 * 2 + (e & 1)] += ex;
                        acc[mi][n8][e] = 0.f;
                    }
#pragma unroll
            for (int off = 4; off < 32; off <<= 1)
#pragma unroll
                for (int i = 0; i < 8; ++i)
                    colpart[i] += __shfl_xor_sync(0xffffffffu, colpart[i], off);
            if (lane < 4) {
                const int tb = tt * 64 + wn * 32;
#pragma unroll
                for (int i = 0; i < 8; ++i)
                    atomicAdd(&s_colsum[tb + (i >> 1) * 8 + (i & 1) + lane * 2], colpart[i]);
            }
            if ((st & 63) == 63) {
                // strip end: flush rowpart
                const int strip = st >> 6;
#pragma unroll
                for (int off = 1; off < 4; off <<= 1)
#pragma unroll
                    for (int i = 0; i < 8; ++i)
                        rowpart[i] += __shfl_xor_sync(0xffffffffu, rowpart[i], off);
                if ((lane & 3) == 0) {
#pragma unroll
                    for (int i = 0; i < 8; ++i) {
                        int v = strip * 256 + wm * 64 + (i >> 1) * 16 + (i & 1) * 8 + (lane >> 2);
                        atomicAdd(&s_rowsum[v], rowpart[i]);
                    }
                }
#pragma unroll
                for (int i = 0; i < 8; ++i) rowpart[i] = 0.f;
            }
        }

        uint32_t t;
        t = A0;  A0 = A1;   A1 = A2;   A2 = t;
        t = Bb0; Bb0 = Bb1; Bb1 = Bb2; Bb2 = t;
    }
    __syncthreads();

    // flush rowsum to global; colsum -> 0.5 * sum(log) scalar
    atomicAdd(&g_rowsum[bp * 512 + tid], s_rowsum[tid]);
    atomicAdd(&g_rowsum[bp * 512 + tid + 256], s_rowsum[tid + 256]);

    float lc = logf(s_colsum[tid & 255]);
    if (tid >= 256) lc = 0.f;   // unreachable (256 threads) but safe
    lc = warp_reduce_sum(lc);
    if (lane == 0) s_red[warp] = lc;
    __syncthreads();
    if (tid == 0) {
        float tot = 0.f;
#pragma unroll
        for (int w = 0; w < 8; ++w) tot += s_red[w];
        atomicAdd(&g_acc[bp], 0.5f * tot);
    }
}

// ---------------------------------------------------------------------------
// Kernel 4: clip_reduce. clip[bp] = (0.5*sum log rowsum + g_acc - g_diag)/512
// ---------------------------------------------------------------------------
__global__ void clip_reduce_kernel() {
    const int bp = blockIdx.x, tid = threadIdx.x;   // 128 threads
    float s = 0.f;
#pragma unroll
    for (int i = 0; i < 4; ++i) s += logf(g_rowsum[bp * 512 + tid + i * 128]);
    s = warp_reduce_sum(s);
    __shared__ float sr[4];
    if ((tid & 31) == 0) sr[tid >> 5] = s;
    __syncthreads();
    if (tid == 0) {
        float tot = sr[0] + sr[1] + sr[2] + sr[3];
        g_clip[bp] = (0.5f * tot + g_acc[bp] - g_diag[bp]) * (1.0f / 512.0f);
    }
}

// ---------------------------------------------------------------------------
// Kernel 5: finalize. loss = mean((output-clip)^2); acc; preds broadcast.
// ---------------------------------------------------------------------------
__global__ void finalize_kernel(const float* __restrict__ output,
                                float* __restrict__ out, int out_size) {
    __shared__ float s_sq[8];
    __shared__ int s_pred[16];
    __shared__ int s_match;
    const int tid = threadIdx.x;
    const int lane = tid & 31, warp = tid >> 5;
    if (tid == 0) s_match = 0;
    __syncthreads();

    float d = output[tid] - g_clip[tid];
    float sq = warp_reduce_sum(d * d);
    if (lane == 0) s_sq[warp] = sq;

    if (tid < 16) {
        int b = tid;
        float bo = output[b * 16], bc = g_clip[b * 16];
        int po = 0, pcidx = 0;
#pragma unroll
        for (int c = 1; c < 16; ++c) {
            float o = output[b * 16 + c];
            if (o < bo) { bo = o; po = c; }
            float cl = g_clip[b * 16 + c];
            if (cl < bc) { bc = cl; pcidx = c; }
        }
        s_pred[b] = po;
        if (po == pcidx) atomicAdd(&s_match, 1);
    }
    __syncthreads();

    if (tid == 0) {
        float tot = 0.f;
#pragma unroll
        for (int w = 0; w < 8; ++w) tot += s_sq[w];
        if (out_size > 0) out[0] = tot * (1.0f / 256.0f);
        if (out_size > 1) out[1] = (float)s_match * (100.0f / 16.0f);
    }
    for (int idx = tid; idx < 8192; idx += 256) {
        int b = idx >> 9;
        if (idx + 2 < out_size) out[idx + 2] = (float)s_pred[b];
    }
}

// ---------------------------------------------------------------------------
extern "C" void kernel_launch(void* const* d_in, const int* in_sizes, int n_in,
                              void* d_out, int out_size) {
    const float* output = (const float*)d_in[0];        // (B, C)
    const float* text   = (const float*)d_in[1];        // (B, S, C, D)
    const float* vis    = (const float*)d_in[2];        // (B, S, D)
    float* out = (float*)d_out;

    cudaFuncSetAttribute(clip_gemm_kernel, cudaFuncAttributeMaxDynamicSharedMemorySize, DYN_BYTES);

    norm_vis_kernel<<<(B_ * S_) / 8, 256>>>(vis);
    norm_text_kernel<<<(B_ * S_ * C_) / 8, 256>>>(text);
    clip_gemm_kernel<<<2 * B_ * C_, 256, DYN_BYTES>>>();
    clip_reduce_kernel<<<B_ * C_, 128>>>();
    finalize_kernel<<<1, 256>>>(output, out, out_size);
}